// round 8
// baseline (speedup 1.0000x reference)
#include <cuda_runtime.h>
#include <math.h>

#define Bc 8
#define Nc 16384
#define Cc 96
#define Hh 4
#define Dd 24
#define WIMG 128
#define XP 132           // smem row pitch (floats): 16B-aligned rows
#define NT 1024
#define KVP 584          // kv_s per-head pitch

// rope: theta_k = 10000^(-k/48); angle = (n mod 128) * theta_k
#define THL 0.27682734124061354f   // log2(10000)/48

// ---- fused global scratch: [0,18432) = kv[b][h][24][24], [18432,19200) = ksum[b][96]
#define ACC_KV 0
#define ACC_KS 18432
#define ACC_SZ 19200
__device__ float g_accum[ACC_SZ];

typedef unsigned long long u64;

__device__ __forceinline__ u64 pk2(float lo, float hi) {
    u64 r; asm("mov.b64 %0,{%1,%2};" : "=l"(r) : "f"(lo), "f"(hi)); return r;
}
__device__ __forceinline__ void upk2(u64 v, float& lo, float& hi) {
    asm("mov.b64 {%0,%1},%2;" : "=f"(lo), "=f"(hi) : "l"(v));
}
__device__ __forceinline__ u64 fma2(u64 a, u64 b, u64 c) {
    u64 d; asm("fma.rn.f32x2 %0,%1,%2,%3;" : "=l"(d) : "l"(a), "l"(b), "l"(c)); return d;
}
__device__ __forceinline__ float elu1(float x) { return x > 0.f ? x + 1.f : expf(x); }

// ---------------- K1: k-half GEMM + ksum + kv reduction ----------------
// smem: x_s[96*XP] | w_s[9216] | b_s[96] | kr_s[96*XP] | ks_s[96]
#define K1_SMEM ((12672 + 9216 + 96 + 12672 + 96) * 4)

__global__ void __launch_bounds__(NT, 1)
k_stats(const float* __restrict__ xg, const float* __restrict__ wg,
        const float* __restrict__ bg) {
    extern __shared__ float smem[];
    float* x_s  = smem;
    float* w_s  = smem + 12672;
    float* b_s  = w_s + 9216;
    float* kr_s = b_s + 96;
    float* ks_s = kr_s + 12672;

    int tid = threadIdx.x;
    int r = blockIdx.x, b = blockIdx.y;
    const float* xrow = xg + ((size_t)b * Nc + (size_t)r * WIMG) * Cc;

    for (int i = tid; i < WIMG * Cc; i += NT) {
        int t = i / Cc, c = i % Cc;
        x_s[c * XP + t] = xrow[i];
    }
    for (int i = tid; i < Cc * Cc; i += NT) {
        int j = i / Cc, c = i % Cc;
        w_s[c * Cc + j] = wg[(Cc + j) * Cc + c];
    }
    if (tid < Cc) { b_s[tid] = bg[Cc + tid]; ks_s[tid] = 0.f; }
    __syncthreads();

    // GEMM: t-fastest warp layout. Each thread: token t0, channels j0..j0+11.
    int t0 = tid & 127;
    int j0 = (tid >> 7) * 12;

    u64 acc[6];
#pragma unroll
    for (int jj = 0; jj < 6; jj++)
        acc[jj] = pk2(b_s[j0 + 2 * jj], b_s[j0 + 2 * jj + 1]);

#pragma unroll 4
    for (int c = 0; c < Cc; c++) {
        float xv = x_s[c * XP + t0];
        u64 xd = pk2(xv, xv);
        const u64* wr = (const u64*)&w_s[c * Cc + j0];
        acc[0] = fma2(xd, wr[0], acc[0]);
        acc[1] = fma2(xd, wr[1], acc[1]);
        acc[2] = fma2(xd, wr[2], acc[2]);
        acc[3] = fma2(xd, wr[3], acc[3]);
        acc[4] = fma2(xd, wr[4], acc[4]);
        acc[5] = fma2(xd, wr[5], acc[5]);
    }

    // epilogue: elu+1, warp-reduced ksum, inline rope, write k_rope
    int lane = tid & 31;
#pragma unroll
    for (int jj = 0; jj < 6; jj++) {
        int ch = j0 + 2 * jj;
        int kk = ch >> 1;
        float theta = exp2f(-(float)kk * THL);
        float a0, a1; upk2(acc[jj], a0, a1);
        float k0 = elu1(a0), k1 = elu1(a1);
        float sv, cv; sincosf((float)t0 * theta, &sv, &cv);
        kr_s[ch * XP + t0]       = k0 * cv - k1 * sv;
        kr_s[(ch + 1) * XP + t0] = k0 * sv + k1 * cv;
        // warp reduce over the 32 tokens in this warp (all lanes same ch)
        float s0 = k0, s1 = k1;
#pragma unroll
        for (int off = 16; off; off >>= 1) {
            s0 += __shfl_xor_sync(0xffffffffu, s0, off);
            s1 += __shfl_xor_sync(0xffffffffu, s1, off);
        }
        if (lane == 0) {
            atomicAdd(&ks_s[ch], s0);
            atomicAdd(&ks_s[ch + 1], s1);
        }
    }
    __syncthreads();

    if (tid < Cc) atomicAdd(&g_accum[ACC_KS + b * Cc + tid], ks_s[tid]);

    // kv: 4 heads x 64 cells x 4 segments of 32 tokens (float4 loads)
    int h = tid >> 8, q = tid & 255;
    int cell = q & 63, seg = q >> 6;
    int d0 = (cell & 7) * 3, e0 = (cell >> 3) * 3;
    int tq0 = seg * 32;
    u64 a2[3][3];
#pragma unroll
    for (int i = 0; i < 3; i++)
#pragma unroll
        for (int j = 0; j < 3; j++) a2[i][j] = 0ull;

    const float* krb = &kr_s[(h * Dd + d0) * XP + tq0];
    const float* xb  = &x_s[(h * Dd + e0) * XP + tq0];
#pragma unroll 2
    for (int i = 0; i < 8; i++) {
        float4 kA = *(const float4*)&krb[4 * i];
        float4 kB = *(const float4*)&krb[XP + 4 * i];
        float4 kC = *(const float4*)&krb[2 * XP + 4 * i];
        float4 xA = *(const float4*)&xb[4 * i];
        float4 xB = *(const float4*)&xb[XP + 4 * i];
        float4 xC = *(const float4*)&xb[2 * XP + 4 * i];
        u64 kr0a = pk2(kA.x, kA.y), kr0b = pk2(kA.z, kA.w);
        u64 kr1a = pk2(kB.x, kB.y), kr1b = pk2(kB.z, kB.w);
        u64 kr2a = pk2(kC.x, kC.y), kr2b = pk2(kC.z, kC.w);
        u64 xv0a = pk2(xA.x, xA.y), xv0b = pk2(xA.z, xA.w);
        u64 xv1a = pk2(xB.x, xB.y), xv1b = pk2(xB.z, xB.w);
        u64 xv2a = pk2(xC.x, xC.y), xv2b = pk2(xC.z, xC.w);
        a2[0][0] = fma2(kr0a, xv0a, a2[0][0]); a2[0][0] = fma2(kr0b, xv0b, a2[0][0]);
        a2[0][1] = fma2(kr0a, xv1a, a2[0][1]); a2[0][1] = fma2(kr0b, xv1b, a2[0][1]);
        a2[0][2] = fma2(kr0a, xv2a, a2[0][2]); a2[0][2] = fma2(kr0b, xv2b, a2[0][2]);
        a2[1][0] = fma2(kr1a, xv0a, a2[1][0]); a2[1][0] = fma2(kr1b, xv0b, a2[1][0]);
        a2[1][1] = fma2(kr1a, xv1a, a2[1][1]); a2[1][1] = fma2(kr1b, xv1b, a2[1][1]);
        a2[1][2] = fma2(kr1a, xv2a, a2[1][2]); a2[1][2] = fma2(kr1b, xv2b, a2[1][2]);
        a2[2][0] = fma2(kr2a, xv0a, a2[2][0]); a2[2][0] = fma2(kr2b, xv0b, a2[2][0]);
        a2[2][1] = fma2(kr2a, xv1a, a2[2][1]); a2[2][1] = fma2(kr2b, xv1b, a2[2][1]);
        a2[2][2] = fma2(kr2a, xv2a, a2[2][2]); a2[2][2] = fma2(kr2b, xv2b, a2[2][2]);
    }
    float* kvb_g = &g_accum[ACC_KV + ((size_t)b * Hh + h) * Dd * Dd];
#pragma unroll
    for (int i = 0; i < 3; i++)
#pragma unroll
        for (int j = 0; j < 3; j++) {
            float lo, hi; upk2(a2[i][j], lo, hi);
            atomicAdd(&kvb_g[(d0 + i) * Dd + e0 + j], lo + hi);
        }
}

// ---------------- K2: q-half GEMM + z + matvec(kv) + LePE + store ----------------
// smem: x_s[12672] | wu[12672](w then row r-1) | qr_s[12672] | xp_s[12672]
//       | kv_s[4*KVP] | b_s[96] | za[512]
#define K2_SMEM ((12672 * 4 + 4 * KVP + 96 + 512) * 4)

__global__ void __launch_bounds__(NT, 1)
k_out(const float* __restrict__ xg, const float* __restrict__ wg,
      const float* __restrict__ bg, const float* __restrict__ lwg,
      const float* __restrict__ lbg, float* __restrict__ og) {
    extern __shared__ float smem[];
    float* x_s  = smem;           // [c*XP + t]
    float* wu   = smem + 12672;   // weights [c*96+j], later row r-1 [c*XP+t]
    float* qr_s = smem + 25344;
    float* xp_s = smem + 38016;   // row r+1
    float* kv_s = xp_s + 12672;   // [4][KVP]
    float* b_s  = kv_s + 4 * KVP;
    float* za   = b_s + 96;       // [128][4]

    int tid = threadIdx.x;
    int r = blockIdx.x, bb = blockIdx.y;
    const float* xrow = xg + ((size_t)bb * Nc + (size_t)r * WIMG) * Cc;

    for (int i = tid; i < WIMG * Cc; i += NT) {
        int t = i / Cc, c = i % Cc;
        x_s[c * XP + t] = xrow[i];
    }
    {
        bool ok = (r + 1) < WIMG;
        const float* xq = xrow + (size_t)WIMG * Cc;
        for (int i = tid; i < WIMG * Cc; i += NT) {
            int t = i / Cc, c = i % Cc;
            xp_s[c * XP + t] = ok ? xq[i] : 0.f;
        }
    }
    for (int i = tid; i < Cc * Cc; i += NT) {
        int j = i / Cc, c = i % Cc;
        wu[c * Cc + j] = wg[j * Cc + c];
    }
    if (tid < Cc) b_s[tid] = bg[tid];
    if (tid < 512) za[tid] = 0.f;
    for (int i = tid; i < Hh * Dd * Dd; i += NT)
        kv_s[(i / 576) * KVP + (i % 576)] =
            g_accum[ACC_KV + (size_t)bb * Hh * Dd * Dd + i];
    __syncthreads();

    // GEMM: t-fastest warp layout
    int t0 = tid & 127;
    int j0 = (tid >> 7) * 12;
    int head = j0 / Dd;           // j0 in {0,12,...,84}: channels within one head

    u64 acc[6];
#pragma unroll
    for (int jj = 0; jj < 6; jj++)
        acc[jj] = pk2(b_s[j0 + 2 * jj], b_s[j0 + 2 * jj + 1]);

#pragma unroll 4
    for (int c = 0; c < Cc; c++) {
        float xv = x_s[c * XP + t0];
        u64 xd = pk2(xv, xv);
        const u64* wr = (const u64*)&wu[c * Cc + j0];
        acc[0] = fma2(xd, wr[0], acc[0]);
        acc[1] = fma2(xd, wr[1], acc[1]);
        acc[2] = fma2(xd, wr[2], acc[2]);
        acc[3] = fma2(xd, wr[3], acc[3]);
        acc[4] = fma2(xd, wr[4], acc[4]);
        acc[5] = fma2(xd, wr[5], acc[5]);
    }

    // epilogue: elu+1, z partial vs k_mean, inline rope, write q_rope
    const float inv_n = 1.f / (float)Nc;
    float zp = 0.f;
#pragma unroll
    for (int jj = 0; jj < 6; jj++) {
        int ch = j0 + 2 * jj;
        int kk = ch >> 1;
        float theta = exp2f(-(float)kk * THL);
        float a0, a1; upk2(acc[jj], a0, a1);
        float q0 = elu1(a0), q1 = elu1(a1);
        float km0 = g_accum[ACC_KS + bb * Cc + ch] * inv_n;
        float km1 = g_accum[ACC_KS + bb * Cc + ch + 1] * inv_n;
        zp += q0 * km0 + q1 * km1;
        float sv, cv; sincosf((float)t0 * theta, &sv, &cv);
        qr_s[ch * XP + t0]       = q0 * cv - q1 * sv;
        qr_s[(ch + 1) * XP + t0] = q0 * sv + q1 * cv;
    }
    atomicAdd(&za[t0 * 4 + head], zp);
    __syncthreads();

    // stage row r-1 into wu (weights no longer needed)
    {
        bool ok = r > 0;
        const float* xq = xrow - (size_t)WIMG * Cc;
        for (int i = tid; i < WIMG * Cc; i += NT) {
            int t = i / Cc, c = i % Cc;
            wu[c * XP + t] = ok ? xq[i] : 0.f;
        }
    }
    __syncthreads();

    // matvec: out[t0][e] = sum_d q_rope[t0][h*24+d] * kv[h][d][e], e = j0%24 .. +11
    int e0 = j0 % Dd;
    u64 mv[6];
#pragma unroll
    for (int jj = 0; jj < 6; jj++) mv[jj] = 0ull;

    const float* qb  = &qr_s[(head * Dd) * XP + t0];
    const float* kvb = &kv_s[head * KVP + e0];
#pragma unroll 4
    for (int d = 0; d < Dd; d++) {
        float qv = qb[d * XP];
        u64 xd = pk2(qv, qv);
        const u64* kvr = (const u64*)(kvb + d * Dd);
        mv[0] = fma2(xd, kvr[0], mv[0]);
        mv[1] = fma2(xd, kvr[1], mv[1]);
        mv[2] = fma2(xd, kvr[2], mv[2]);
        mv[3] = fma2(xd, kvr[3], mv[3]);
        mv[4] = fma2(xd, kvr[4], mv[4]);
        mv[5] = fma2(xd, kvr[5], mv[5]);
    }

    // scale by z/n
    float attn[12];
    {
        float s = inv_n / (za[t0 * 4 + head] + 1e-6f);
#pragma unroll
        for (int jj = 0; jj < 6; jj++) {
            float a0, a1; upk2(mv[jj], a0, a1);
            attn[2 * jj]     = a0 * s;
            attn[2 * jj + 1] = a1 * s;
        }
    }

    // LePE: depthwise 3x3, predicated edge loads (window t0-1..t0+1)
    bool inl = t0 > 0, inr = t0 < 127;
#pragma unroll
    for (int c6 = 0; c6 < 12; c6++) {
        int ch = j0 + c6;
        const float* w9 = &lwg[ch * 9];
        const float* mrow = &wu[ch * XP + t0];
        const float* crow = &x_s[ch * XP + t0];
        const float* prow = &xp_s[ch * XP + t0];
        float m0 = inl ? mrow[-1] : 0.f, m1 = mrow[0], m2 = inr ? mrow[1] : 0.f;
        float c0 = inl ? crow[-1] : 0.f, c1 = crow[0], c2 = inr ? crow[1] : 0.f;
        float p0 = inl ? prow[-1] : 0.f, p1 = prow[0], p2 = inr ? prow[1] : 0.f;
        float lep = w9[0] * m0 + w9[1] * m1 + w9[2] * m2
                  + w9[3] * c0 + w9[4] * c1 + w9[5] * c2
                  + w9[6] * p0 + w9[7] * p1 + w9[8] * p2;
        attn[c6] += lep + lbg[ch];
    }

    // store 12 floats = 3 x float4
    float* o = og + ((size_t)bb * Nc + (size_t)r * WIMG + t0) * Cc + j0;
#pragma unroll
    for (int v = 0; v < 3; v++) {
        float4 q4 = make_float4(attn[4 * v], attn[4 * v + 1],
                                attn[4 * v + 2], attn[4 * v + 3]);
        *(float4*)(o + 4 * v) = q4;
    }
}

// ---------------- launch ----------------
extern "C" void kernel_launch(void* const* d_in, const int* in_sizes, int n_in,
                              void* d_out, int out_size) {
    const float* x    = (const float*)d_in[0];
    const float* qk_w = (const float*)d_in[1];
    const float* qk_b = (const float*)d_in[2];
    const float* lw   = (const float*)d_in[3];
    const float* lb   = (const float*)d_in[4];
    float* out = (float*)d_out;

    cudaFuncSetAttribute(k_stats, cudaFuncAttributeMaxDynamicSharedMemorySize, K1_SMEM);
    cudaFuncSetAttribute(k_out,   cudaFuncAttributeMaxDynamicSharedMemorySize, K2_SMEM);

    void* accp = nullptr;
    cudaGetSymbolAddress(&accp, g_accum);
    cudaMemsetAsync(accp, 0, ACC_SZ * sizeof(float), 0);

    dim3 grid(WIMG, Bc);
    k_stats<<<grid, NT, K1_SMEM>>>(x, qk_w, qk_b);
    k_out<<<grid, NT, K2_SMEM>>>(x, qk_w, qk_b, lw, lb, out);
}

// round 10
// speedup vs baseline: 1.3500x; 1.3500x over previous
#include <cuda_runtime.h>
#include <math.h>

#define Bc 8
#define Nc 16384
#define Cc 96
#define Hh 4
#define Dd 24
#define WIMG 128
#define XP 130           // smem row pitch (floats)
#define NT 512
#define KVP 584          // kv_s per-head pitch

// rope: theta_k = 10000^(-k/48); angle = (n mod 128) * theta_k
#define THL 0.27682734124061354f   // log2(10000)/48

// ---- fused global scratch: [0,18432) = kv[b][h][24][24], [18432,19200) = ksum[b][96]
#define ACC_KV 0
#define ACC_KS 18432
#define ACC_SZ 19200
__device__ float g_accum[ACC_SZ];

typedef unsigned long long u64;

__device__ __forceinline__ u64 pk2(float lo, float hi) {
    u64 r; asm("mov.b64 %0,{%1,%2};" : "=l"(r) : "f"(lo), "f"(hi)); return r;
}
__device__ __forceinline__ void upk2(u64 v, float& lo, float& hi) {
    asm("mov.b64 {%0,%1},%2;" : "=f"(lo), "=f"(hi) : "l"(v));
}
__device__ __forceinline__ u64 fma2(u64 a, u64 b, u64 c) {
    u64 d; asm("fma.rn.f32x2 %0,%1,%2,%3;" : "=l"(d) : "l"(a), "l"(b), "l"(c)); return d;
}
__device__ __forceinline__ float elu1(float x) { return x > 0.f ? x + 1.f : __expf(x); }

// ---------------- K1: k-half GEMM + ksum + kv reduction ----------------
// smem: x_s[96][XP] | w_s[96][96] | b_s[96] | kr_s[96][XP] | ks_s[96]
#define K1_SMEM ((12480 + 9216 + 96 + 12480 + 96) * 4)

__global__ void __launch_bounds__(NT, 1)
k_stats(const float* __restrict__ xg, const float* __restrict__ wg,
        const float* __restrict__ bg) {
    extern __shared__ float smem[];
    float* x_s  = smem;
    float* w_s  = smem + 12480;
    float* b_s  = w_s + 9216;
    float* kr_s = b_s + 96;
    float* ks_s = kr_s + 12480;

    int tid = threadIdx.x;
    int r = blockIdx.x, b = blockIdx.y;
    const float* xrow = xg + ((size_t)b * Nc + (size_t)r * WIMG) * Cc;

    for (int i = tid; i < WIMG * Cc; i += NT) {
        int t = i / Cc, c = i % Cc;
        x_s[c * XP + t] = xrow[i];
    }
    for (int i = tid; i < Cc * Cc; i += NT) {
        int j = i / Cc, c = i % Cc;
        w_s[c * Cc + j] = wg[(Cc + j) * Cc + c];
    }
    if (tid < Cc) { b_s[tid] = bg[Cc + tid]; ks_s[tid] = 0.f; }
    __syncthreads();

    int g_j = tid & 15, g_t = tid >> 4;
    int j0 = g_j * 6, t0 = g_t * 4;

    u64 acc[4][3];
#pragma unroll
    for (int tt = 0; tt < 4; tt++)
#pragma unroll
        for (int jj = 0; jj < 3; jj++)
            acc[tt][jj] = pk2(b_s[j0 + 2 * jj], b_s[j0 + 2 * jj + 1]);

#pragma unroll 4
    for (int c = 0; c < Cc; c++) {
        const float* xr = &x_s[c * XP + t0];
        const u64* wr = (const u64*)&w_s[c * Cc + j0];
        u64 w0 = wr[0], w1 = wr[1], w2 = wr[2];
#pragma unroll
        for (int tt = 0; tt < 4; tt++) {
            float xv = xr[tt];
            u64 xd = pk2(xv, xv);
            acc[tt][0] = fma2(xd, w0, acc[tt][0]);
            acc[tt][1] = fma2(xd, w1, acc[tt][1]);
            acc[tt][2] = fma2(xd, w2, acc[tt][2]);
        }
    }

    // epilogue: elu+1, ksum partials, inline rope (MUFU), write k_rope
#pragma unroll
    for (int jj = 0; jj < 3; jj++) {
        int ch = j0 + 2 * jj;
        int kk = ch >> 1;
        float theta = exp2f(-(float)kk * THL);
        float s0 = 0.f, s1 = 0.f;
#pragma unroll
        for (int tt = 0; tt < 4; tt++) {
            int t = t0 + tt;
            float a0, a1; upk2(acc[tt][jj], a0, a1);
            float k0 = elu1(a0), k1 = elu1(a1);
            s0 += k0; s1 += k1;
            float a = (float)t * theta;
            float sv = __sinf(a), cv = __cosf(a);
            kr_s[ch * XP + t]       = k0 * cv - k1 * sv;
            kr_s[(ch + 1) * XP + t] = k0 * sv + k1 * cv;
        }
        atomicAdd(&ks_s[ch], s0);
        atomicAdd(&ks_s[ch + 1], s1);
    }
    __syncthreads();

    if (tid < Cc) atomicAdd(&g_accum[ACC_KS + b * Cc + tid], ks_s[tid]);

    // kv: 4 heads x 128 threads; each thread 3x3 cells over half the token pairs
    int h = tid >> 7, q = tid & 127;
    int cell = q & 63, half = q >> 6;
    int d0 = (cell & 7) * 3, e0 = (cell >> 3) * 3;
    int tp0 = half * 32;
    u64 a2[3][3];
#pragma unroll
    for (int i = 0; i < 3; i++)
#pragma unroll
        for (int j = 0; j < 3; j++) a2[i][j] = 0ull;

    const float* krb = &kr_s[(h * Dd + d0) * XP];
    const float* xb  = &x_s[(h * Dd + e0) * XP];
#pragma unroll 4
    for (int tp = tp0; tp < tp0 + 32; tp++) {
        u64 kr0 = *(const u64*)&krb[2 * tp];
        u64 kr1 = *(const u64*)&krb[XP + 2 * tp];
        u64 kr2 = *(const u64*)&krb[2 * XP + 2 * tp];
        u64 xv0 = *(const u64*)&xb[2 * tp];
        u64 xv1 = *(const u64*)&xb[XP + 2 * tp];
        u64 xv2 = *(const u64*)&xb[2 * XP + 2 * tp];
        a2[0][0] = fma2(kr0, xv0, a2[0][0]);
        a2[0][1] = fma2(kr0, xv1, a2[0][1]);
        a2[0][2] = fma2(kr0, xv2, a2[0][2]);
        a2[1][0] = fma2(kr1, xv0, a2[1][0]);
        a2[1][1] = fma2(kr1, xv1, a2[1][1]);
        a2[1][2] = fma2(kr1, xv2, a2[1][2]);
        a2[2][0] = fma2(kr2, xv0, a2[2][0]);
        a2[2][1] = fma2(kr2, xv1, a2[2][1]);
        a2[2][2] = fma2(kr2, xv2, a2[2][2]);
    }
    float* kvb_g = &g_accum[ACC_KV + ((size_t)b * Hh + h) * Dd * Dd];
#pragma unroll
    for (int i = 0; i < 3; i++)
#pragma unroll
        for (int j = 0; j < 3; j++) {
            float lo, hi; upk2(a2[i][j], lo, hi);
            atomicAdd(&kvb_g[(d0 + i) * Dd + e0 + j], lo + hi);
        }
}

// ---------------- K2: q-half GEMM + z + matvec(kv) + LePE + store ----------------
// smem: x_s[12480](halo) | wu[12480](w then row r-1) | qr_s[12480] | xp_s[12480]
//       | kv_s[4*KVP] | b_s[96] | za[512]
#define K2_SMEM ((12480 * 4 + 4 * KVP + 96 + 512) * 4)

__global__ void __launch_bounds__(NT, 1)
k_out(const float* __restrict__ xg, const float* __restrict__ wg,
      const float* __restrict__ bg, const float* __restrict__ lwg,
      const float* __restrict__ lbg, float* __restrict__ og) {
    extern __shared__ float smem[];
    float* x_s  = smem;           // halo layout: col t at [c*XP + 1 + t]
    float* wu   = smem + 12480;   // weights, later row r-1
    float* qr_s = smem + 24960;
    float* xp_s = smem + 37440;   // row r+1 (halo layout)
    float* kv_s = smem + 49920;   // [4][KVP]
    float* b_s  = kv_s + 4 * KVP;
    float* za   = b_s + 96;       // [128][4]

    int tid = threadIdx.x;
    int r = blockIdx.x, bb = blockIdx.y;
    const float* xrow = xg + ((size_t)bb * Nc + (size_t)r * WIMG) * Cc;

    for (int i = tid; i < WIMG * Cc; i += NT) {
        int t = i / Cc, c = i % Cc;
        x_s[c * XP + 1 + t] = xrow[i];
    }
    {
        bool ok = (r + 1) < WIMG;
        const float* xq = xrow + (size_t)WIMG * Cc;
        for (int i = tid; i < WIMG * Cc; i += NT) {
            int t = i / Cc, c = i % Cc;
            xp_s[c * XP + 1 + t] = ok ? xq[i] : 0.f;
        }
    }
    for (int i = tid; i < Cc * Cc; i += NT) {
        int j = i / Cc, c = i % Cc;
        wu[c * Cc + j] = wg[j * Cc + c];
    }
    if (tid < Cc) {
        b_s[tid] = bg[tid];
        x_s[tid * XP] = 0.f;  x_s[tid * XP + 129] = 0.f;
        xp_s[tid * XP] = 0.f; xp_s[tid * XP + 129] = 0.f;
    }
    if (tid < 128) {
        za[tid * 4] = 0.f; za[tid * 4 + 1] = 0.f;
        za[tid * 4 + 2] = 0.f; za[tid * 4 + 3] = 0.f;
    }
    for (int i = tid; i < Hh * Dd * Dd; i += NT)
        kv_s[(i / 576) * KVP + (i % 576)] =
            g_accum[ACC_KV + (size_t)bb * Hh * Dd * Dd + i];
    __syncthreads();

    int g_j = tid & 15, g_t = tid >> 4;
    int j0 = g_j * 6, t0 = g_t * 4;
    int head = j0 / Dd, e0 = j0 % Dd;

    u64 acc[4][3];
#pragma unroll
    for (int tt = 0; tt < 4; tt++)
#pragma unroll
        for (int jj = 0; jj < 3; jj++)
            acc[tt][jj] = pk2(b_s[j0 + 2 * jj], b_s[j0 + 2 * jj + 1]);

#pragma unroll 4
    for (int c = 0; c < Cc; c++) {
        const float* xr = &x_s[c * XP + 1 + t0];
        const u64* wr = (const u64*)&wu[c * Cc + j0];
        u64 w0 = wr[0], w1 = wr[1], w2 = wr[2];
#pragma unroll
        for (int tt = 0; tt < 4; tt++) {
            float xv = xr[tt];
            u64 xd = pk2(xv, xv);
            acc[tt][0] = fma2(xd, w0, acc[tt][0]);
            acc[tt][1] = fma2(xd, w1, acc[tt][1]);
            acc[tt][2] = fma2(xd, w2, acc[tt][2]);
        }
    }

    // epilogue: elu+1, z partial vs k_mean, inline rope (MUFU), write q_rope
    const float inv_n = 1.f / (float)Nc;
    float km[6];
#pragma unroll
    for (int i = 0; i < 6; i++) km[i] = g_accum[ACC_KS + bb * Cc + j0 + i] * inv_n;

    float zp[4] = {0.f, 0.f, 0.f, 0.f};
#pragma unroll
    for (int jj = 0; jj < 3; jj++) {
        int ch = j0 + 2 * jj;
        int kk = ch >> 1;
        float theta = exp2f(-(float)kk * THL);
#pragma unroll
        for (int tt = 0; tt < 4; tt++) {
            int t = t0 + tt;
            float a0, a1; upk2(acc[tt][jj], a0, a1);
            float q0 = elu1(a0), q1 = elu1(a1);
            zp[tt] += q0 * km[2 * jj] + q1 * km[2 * jj + 1];
            float a = (float)t * theta;
            float sv = __sinf(a), cv = __cosf(a);
            qr_s[ch * XP + t]       = q0 * cv - q1 * sv;
            qr_s[(ch + 1) * XP + t] = q0 * sv + q1 * cv;
        }
    }
#pragma unroll
    for (int tt = 0; tt < 4; tt++)
        atomicAdd(&za[(t0 + tt) * 4 + head], zp[tt]);
    __syncthreads();

    // stage row r-1 into wu (weights no longer needed)
    {
        bool ok = r > 0;
        const float* xq = xrow - (size_t)WIMG * Cc;
        for (int i = tid; i < WIMG * Cc; i += NT) {
            int t = i / Cc, c = i % Cc;
            wu[c * XP + 1 + t] = ok ? xq[i] : 0.f;
        }
        if (tid < Cc) { wu[tid * XP] = 0.f; wu[tid * XP + 129] = 0.f; }
    }
    __syncthreads();

    // matvec: out[t][e] = sum_d q_rope[t][h*24+d] * kv[h][d][e]
    u64 mv[4][3];
#pragma unroll
    for (int tt = 0; tt < 4; tt++)
#pragma unroll
        for (int jj = 0; jj < 3; jj++) mv[tt][jj] = 0ull;

    const float* qb  = &qr_s[(head * Dd) * XP + t0];
    const float* kvb = &kv_s[head * KVP + e0];
#pragma unroll 4
    for (int d = 0; d < Dd; d++) {
        const float* qrow = qb + d * XP;
        const u64* kvr = (const u64*)(kvb + d * Dd);
        u64 w0 = kvr[0], w1 = kvr[1], w2 = kvr[2];
#pragma unroll
        for (int tt = 0; tt < 4; tt++) {
            float qv = qrow[tt];
            u64 xd = pk2(qv, qv);
            mv[tt][0] = fma2(xd, w0, mv[tt][0]);
            mv[tt][1] = fma2(xd, w1, mv[tt][1]);
            mv[tt][2] = fma2(xd, w2, mv[tt][2]);
        }
    }

    // scale by z/n
    float attn[4][6];
#pragma unroll
    for (int tt = 0; tt < 4; tt++) {
        float s = __fdividef(inv_n, za[(t0 + tt) * 4 + head] + 1e-6f);
#pragma unroll
        for (int jj = 0; jj < 3; jj++) {
            float a0, a1; upk2(mv[tt][jj], a0, a1);
            attn[tt][2 * jj]     = a0 * s;
            attn[tt][2 * jj + 1] = a1 * s;
        }
    }

    // LePE: depthwise 3x3 via register sliding windows over staged rows
#pragma unroll
    for (int c6 = 0; c6 < 6; c6++) {
        int ch = j0 + c6;
        float w9[9];
#pragma unroll
        for (int i = 0; i < 9; i++) w9[i] = lwg[ch * 9 + i];
        float lb = lbg[ch];
        const float* m  = &wu[ch * XP + t0];
        const float* cc = &x_s[ch * XP + t0];
        const float* p  = &xp_s[ch * XP + t0];
        float wm[6], wc[6], wp[6];
#pragma unroll
        for (int i = 0; i < 6; i++) { wm[i] = m[i]; wc[i] = cc[i]; wp[i] = p[i]; }
#pragma unroll
        for (int tt = 0; tt < 4; tt++) {
            float lep = w9[0] * wm[tt] + w9[1] * wm[tt + 1] + w9[2] * wm[tt + 2]
                      + w9[3] * wc[tt] + w9[4] * wc[tt + 1] + w9[5] * wc[tt + 2]
                      + w9[6] * wp[tt] + w9[7] * wp[tt + 1] + w9[8] * wp[tt + 2];
            attn[tt][c6] += lep + lb;
        }
    }

    // store
    float* orow = og + ((size_t)bb * Nc + (size_t)r * WIMG) * Cc;
#pragma unroll
    for (int tt = 0; tt < 4; tt++) {
        float* o = orow + (size_t)(t0 + tt) * Cc + j0;
#pragma unroll
        for (int jj = 0; jj < 3; jj++) {
            float2 v = make_float2(attn[tt][2 * jj], attn[tt][2 * jj + 1]);
            *(float2*)(o + 2 * jj) = v;
        }
    }
}

// ---------------- launch ----------------
extern "C" void kernel_launch(void* const* d_in, const int* in_sizes, int n_in,
                              void* d_out, int out_size) {
    const float* x    = (const float*)d_in[0];
    const float* qk_w = (const float*)d_in[1];
    const float* qk_b = (const float*)d_in[2];
    const float* lw   = (const float*)d_in[3];
    const float* lb   = (const float*)d_in[4];
    float* out = (float*)d_out;

    cudaFuncSetAttribute(k_stats, cudaFuncAttributeMaxDynamicSharedMemorySize, K1_SMEM);
    cudaFuncSetAttribute(k_out,   cudaFuncAttributeMaxDynamicSharedMemorySize, K2_SMEM);

    void* accp = nullptr;
    cudaGetSymbolAddress(&accp, g_accum);
    cudaMemsetAsync(accp, 0, ACC_SZ * sizeof(float), 0);

    dim3 grid(WIMG, Bc);
    k_stats<<<grid, NT, K1_SMEM>>>(x, qk_w, qk_b);
    k_out<<<grid, NT, K2_SMEM>>>(x, qk_w, qk_b, lw, lb, out);
}